// round 2
// baseline (speedup 1.0000x reference)
#include <cuda_runtime.h>
#include <cstdint>

#define N_NODE 100000
#define N_NETS 20000
#define NEDGE  200000
// H_NODE=64, H_NET=32, H_PIN=16, O_NODE=32, O_NET=64

// ---------------- scratch (device globals; no runtime allocation) ----------------
__device__ __align__(16) float g_T[N_NETS * 512];    // [n][p*32+o]  41MB, L2-resident
__device__ __align__(16) float g_Bias[N_NETS * 32];  // [n][o] = sum_i nf[n,i]*b2[i,o]
__device__ __align__(16) float g_agg[N_NETS * 64];
__device__ __align__(16) float g_degN[N_NODE];
__device__ __align__(16) float g_degM[N_NETS];
__device__ __align__(16) float g_B[32 * 512];        // W2 rearranged: [i][p*32+o]

__device__ __forceinline__ void red_add_v4(float* addr, float4 v) {
    asm volatile("red.global.add.v4.f32 [%0], {%1, %2, %3, %4};"
                 :: "l"(addr), "f"(v.x), "f"(v.y), "f"(v.z), "f"(v.w)
                 : "memory");
}

// ---------------- zero all accumulators (graph replays must re-zero) ----------------
__global__ void k_zero(float* __restrict__ out) {
    int i = blockIdx.x * blockDim.x + threadIdx.x;
    float4 z = make_float4(0.f, 0.f, 0.f, 0.f);
    if (i < 800000) { ((float4*)out)[i] = z; return; }          // node_out accum region
    i -= 800000;
    if (i < 320000) { ((float4*)g_agg)[i] = z; return; }
    i -= 320000;
    if (i < 25000)  { ((float4*)g_degN)[i] = z; return; }
    i -= 25000;
    if (i < 5000)   { ((float4*)g_degM)[i] = z; return; }
}

// ---------------- W2 [16,1024] -> g_B [32,512] : g_B[i][p*32+o] = W2[p][i*32+o] ----
__global__ void k_rearr(const float* __restrict__ W2) {
    int idx = blockIdx.x * blockDim.x + threadIdx.x;
    if (idx < 16384) {
        int i = idx >> 9;
        int c = idx & 511;
        int p = c >> 5, o = c & 31;
        g_B[idx] = W2[p * 1024 + i * 32 + o];
    }
}

// ---------------- degree counts ----------------
__global__ void k_deg(const int* __restrict__ edge_node, const int* __restrict__ edge_net) {
    int e = blockIdx.x * blockDim.x + threadIdx.x;
    if (e >= NEDGE) return;
    atomicAdd(&g_degN[edge_node[e]], 1.0f);
    atomicAdd(&g_degM[edge_net[e]], 1.0f);
}

// ---------------- T GEMM: T[n, :512] = nf[n, :32] @ g_B; also g_Bias from b2 -------
// block = 128 threads; thread t owns columns [4t, 4t+4); 64 nets per block.
// dyn smem: B (64KB) + nf tile (8KB) + b2 (4KB) = 77824B -> opt-in attribute.
__global__ void __launch_bounds__(128) k_T(const float* __restrict__ net_feat,
                                           const float* __restrict__ b2) {
    extern __shared__ float sm[];
    float* Bs  = sm;                    // 16384 floats
    float* nfs = sm + 16384;            // 2048 floats
    float* b2s = sm + 16384 + 2048;     // 1024 floats
    int t = threadIdx.x;

    float4* Bs4 = (float4*)Bs;
    const float4* gB4 = (const float4*)g_B;
    for (int k = t; k < 4096; k += 128) Bs4[k] = gB4[k];
    for (int k = t; k < 256;  k += 128) ((float4*)b2s)[k] = ((const float4*)b2)[k];

    int n0 = blockIdx.x * 64;
    int nrows = min(64, N_NETS - n0);
    for (int k = t; k < nrows * 8; k += 128)
        ((float4*)nfs)[k] = ((const float4*)net_feat)[n0 * 8 + k];
    __syncthreads();

    for (int ln = 0; ln < nrows; ln++) {
        const float* nr = nfs + ln * 32;
        float4 acc = make_float4(0.f, 0.f, 0.f, 0.f);
#pragma unroll
        for (int i = 0; i < 32; i++) {
            float s = nr[i];
            float4 b = Bs4[i * 128 + t];
            acc.x += s * b.x; acc.y += s * b.y; acc.z += s * b.z; acc.w += s * b.w;
        }
        ((float4*)g_T)[(size_t)(n0 + ln) * 128 + t] = acc;

        if (t < 8) {  // bias term (b2 contribution), 8 float4 columns
            float4 ab = make_float4(0.f, 0.f, 0.f, 0.f);
#pragma unroll
            for (int i = 0; i < 32; i++) {
                float s = nr[i];
                float4 b = ((float4*)b2s)[i * 8 + t];
                ab.x += s * b.x; ab.y += s * b.y; ab.z += s * b.z; ab.w += s * b.w;
            }
            ((float4*)g_Bias)[(n0 + ln) * 8 + t] = ab;
        }
    }
}

// ---------------- relation 1 scatter: agg[net] += node_feat[v] * rsqrt(degN[v]) ----
// 16 lanes per edge, float4 per lane (64 dims); 2 edges per warp.
__global__ void __launch_bounds__(256) k_agg(const float* __restrict__ node_feat,
                                             const int* __restrict__ edge_node,
                                             const int* __restrict__ edge_net) {
    int lane = threadIdx.x & 31;
    int warp = (blockIdx.x * blockDim.x + threadIdx.x) >> 5;
    int g = lane >> 4, j = lane & 15;
    int e = warp * 2 + g;
    if (e >= NEDGE) return;
    int v = edge_node[e];
    int m = edge_net[e];
    float sc = rsqrtf(fmaxf(g_degN[v], 1.0f));
    float4 x = ((const float4*)node_feat)[(size_t)v * 16 + j];
    x.x *= sc; x.y *= sc; x.z *= sc; x.w *= sc;
    red_add_v4(g_agg + m * 64 + j * 4, x);
}

// ---------------- net_out = (agg * rsqrt(degM)) @ W1 + b1 ----------------
// warp per net; lane handles cols (lane, lane+32); W1 in smem.
__global__ void __launch_bounds__(256) k_netout(const float* __restrict__ W1,
                                                const float* __restrict__ b1,
                                                float* __restrict__ net_out) {
    __shared__ float W1s[64 * 64];
    __shared__ float b1s[64];
    int t = threadIdx.x;
    for (int k = t; k < 4096; k += 256) W1s[k] = W1[k];
    if (t < 64) b1s[t] = b1[t];
    __syncthreads();
    int lane = t & 31;
    int n = blockIdx.x * 8 + (t >> 5);
    if (n >= N_NETS) return;
    float sc = rsqrtf(fmaxf(g_degM[n], 1.0f));
    float a0 = g_agg[n * 64 + lane] * sc;
    float a1 = g_agg[n * 64 + 32 + lane] * sc;
    float acc0 = b1s[lane], acc1 = b1s[32 + lane];
#pragma unroll
    for (int k = 0; k < 32; k++) {
        float r = __shfl_sync(0xffffffffu, a0, k);
        acc0 += r * W1s[k * 64 + lane];
        acc1 += r * W1s[k * 64 + 32 + lane];
    }
#pragma unroll
    for (int k = 0; k < 32; k++) {
        float r = __shfl_sync(0xffffffffu, a1, k);
        acc0 += r * W1s[(k + 32) * 64 + lane];
        acc1 += r * W1s[(k + 32) * 64 + 32 + lane];
    }
    net_out[n * 64 + lane]      = acc0;
    net_out[n * 64 + 32 + lane] = acc1;
}

// ---------------- relation 2 per-edge: msg = Bias[n] + pin[e] @ T[n]; scatter ------
// 8 lanes per edge, float4 of outputs per lane; 4 edges per warp.
__global__ void __launch_bounds__(256) k_edge(const float* __restrict__ pin_feat,
                                              const int* __restrict__ edge_node,
                                              const int* __restrict__ edge_net,
                                              float* __restrict__ out) {
    int lane = threadIdx.x & 31;
    int warp = (blockIdx.x * blockDim.x + threadIdx.x) >> 5;
    int g = lane >> 3, j = lane & 7;
    int e = warp * 4 + g;
    if (e >= NEDGE) return;
    int n = edge_net[e];
    int v = edge_node[e];
    const float4* Trow = ((const float4*)g_T) + (size_t)n * 128;
    float4 acc = ((const float4*)g_Bias)[n * 8 + j];
    const float4* pin4 = ((const float4*)pin_feat) + (size_t)e * 4;
#pragma unroll
    for (int q = 0; q < 4; q++) {
        float4 pv = pin4[q];
        float4 t0 = Trow[(4 * q + 0) * 8 + j];
        float4 t1 = Trow[(4 * q + 1) * 8 + j];
        float4 t2 = Trow[(4 * q + 2) * 8 + j];
        float4 t3 = Trow[(4 * q + 3) * 8 + j];
        acc.x += pv.x * t0.x + pv.y * t1.x + pv.z * t2.x + pv.w * t3.x;
        acc.y += pv.x * t0.y + pv.y * t1.y + pv.z * t2.y + pv.w * t3.y;
        acc.z += pv.x * t0.z + pv.y * t1.z + pv.z * t2.z + pv.w * t3.z;
        acc.w += pv.x * t0.w + pv.y * t1.w + pv.z * t2.w + pv.w * t3.w;
    }
    red_add_v4(out + (size_t)v * 32 + j * 4, acc);
}

// ---------------- node_out = accum / clip(degN,1) + b_nn ----------------
__global__ void k_final(const float* __restrict__ b_nn, float* __restrict__ out) {
    int idx = blockIdx.x * blockDim.x + threadIdx.x;
    if (idx >= N_NODE * 8) return;
    int v = idx >> 3, j = idx & 7;
    float inv = 1.0f / fmaxf(g_degN[v], 1.0f);
    float4 o = ((float4*)out)[idx];
    float4 bn = ((const float4*)b_nn)[j];
    o.x = o.x * inv + bn.x;
    o.y = o.y * inv + bn.y;
    o.z = o.z * inv + bn.z;
    o.w = o.w * inv + bn.w;
    ((float4*)out)[idx] = o;
}

extern "C" void kernel_launch(void* const* d_in, const int* in_sizes, int n_in,
                              void* d_out, int out_size) {
    const float* node_feat = (const float*)d_in[0];
    const float* net_feat  = (const float*)d_in[1];
    const float* pin_feat  = (const float*)d_in[2];
    const int*   edge_node = (const int*)d_in[3];
    const int*   edge_net  = (const int*)d_in[4];
    const float* W1   = (const float*)d_in[5];
    const float* b1   = (const float*)d_in[6];
    const float* W2   = (const float*)d_in[7];
    const float* b2   = (const float*)d_in[8];
    const float* b_nn = (const float*)d_in[9];
    float* out = (float*)d_out;

    cudaFuncSetAttribute(k_T, cudaFuncAttributeMaxDynamicSharedMemorySize, 77824);

    k_zero<<<4493, 256>>>(out);
    k_rearr<<<64, 256>>>(W2);
    k_deg<<<782, 256>>>(edge_node, edge_net);
    k_T<<<313, 128, 77824>>>(net_feat, b2);
    k_agg<<<12500, 256>>>(node_feat, edge_node, edge_net);
    k_netout<<<2500, 256>>>(W1, b1, out + (size_t)N_NODE * 32);
    k_edge<<<6250, 256>>>(pin_feat, edge_node, edge_net, out);
    k_final<<<3125, 256>>>(b_nn, out);
}